// round 1
// baseline (speedup 1.0000x reference)
#include <cuda_runtime.h>

// AreaSelfAttention fused kernel (fp32 baseline, f32x2-packed FMA).
// One CTA per 8x8 window. out = gamma * (Wv @ (Xw @ attn^T) + bv) + x
// (uses softmax-rows-sum-to-1 to fold the v-conv past the attention).

#define Cc   256
#define CRc  32
#define Hh   252
#define Ww   252
#define Aa   8
#define LDX  68
#define LDP  68

// smem floats: xs[256][68] + ys[256][68] + qk[64][68] + at[64][68]
#define SMEM_FLOATS (2*Cc*LDX + 2*64*LDP)

static __device__ __forceinline__ unsigned long long pk2(float lo, float hi) {
    unsigned long long r;
    asm("mov.b64 %0, {%1, %2};" : "=l"(r) : "f"(lo), "f"(hi));
    return r;
}
static __device__ __forceinline__ void upk2(unsigned long long v, float& lo, float& hi) {
    asm("mov.b64 {%0, %1}, %2;" : "=f"(lo), "=f"(hi) : "l"(v));
}
static __device__ __forceinline__ void fma2(unsigned long long& d,
                                            unsigned long long a,
                                            unsigned long long b) {
    asm("fma.rn.f32x2 %0, %1, %2, %0;" : "+l"(d) : "l"(a), "l"(b));
}

__global__ __launch_bounds__(256, 1)
void area_attn_kernel(const float* __restrict__ x,
                      const float* __restrict__ Wq, const float* __restrict__ bq,
                      const float* __restrict__ Wk, const float* __restrict__ bk,
                      const float* __restrict__ Wv, const float* __restrict__ bv,
                      const float* __restrict__ gamma,
                      float* __restrict__ out)
{
    extern __shared__ float sm[];
    float* xs = sm;                       // [256][LDX]  padded x window (fp32, kept for residual)
    float* ys = sm + Cc * LDX;            // [256][LDX]  y = Xw @ attn^T
    float* qk = sm + 2 * Cc * LDX;        // [64][LDP]   rows 0..31 = q, 32..63 = k
    float* at = qk + 64 * LDP;            // [64][LDP]   attn[i][j]

    const int t   = threadIdx.x;
    const int blk = blockIdx.x;
    const int bi  = blk >> 10;            // 4096 blocks = 4 * 32 * 32
    const int hi  = (blk >> 5) & 31;
    const int wi  = blk & 31;

    const float* xb = x + (size_t)bi * Cc * Hh * Ww;

    // ---------------- Phase 0: load x window into smem (zero-padded) -------
    // 16384 floats = 4096 float4. Validity is uniform per float4 group since
    // 252 = 31*8 + 4 (edge windows: first 4 cols/rows of last tile valid).
    #pragma unroll
    for (int it = 0; it < 16; ++it) {
        int idx4 = t + (it << 8);
        int c    = idx4 >> 4;          // 16 float4 per channel
        int rem  = idx4 & 15;          // p = rem*4
        int iy   = rem >> 1;
        int ix4  = (rem & 1) << 2;
        int gy   = hi * Aa + iy;
        int gx   = wi * Aa + ix4;
        float4 v = make_float4(0.f, 0.f, 0.f, 0.f);
        if (gy < Hh && gx + 3 < Ww)
            v = *(const float4*)(xb + ((size_t)c * Hh + gy) * Ww + gx);
        *(float4*)(xs + c * LDX + (rem << 2)) = v;
    }
    __syncthreads();

    // ---------------- Phase 1: qk[64][64] = [Wq;Wk] @ Xw + bias ------------
    // thread tile: 4 rows {ty, ty+16, ty+32, ty+48} x 4 cols
    {
        const int ty = t >> 4;
        const int p0 = (t & 15) << 2;
        const float* w0 = Wq + ty * Cc;
        const float* w1 = Wq + (ty + 16) * Cc;
        const float* w2 = Wk + ty * Cc;
        const float* w3 = Wk + (ty + 16) * Cc;
        float acc[4][4];
        #pragma unroll
        for (int r = 0; r < 4; ++r)
            #pragma unroll
            for (int s = 0; s < 4; ++s) acc[r][s] = 0.f;

        for (int c = 0; c < Cc; c += 4) {
            float4 a0 = *(const float4*)(w0 + c);
            float4 a1 = *(const float4*)(w1 + c);
            float4 a2 = *(const float4*)(w2 + c);
            float4 a3 = *(const float4*)(w3 + c);
            #pragma unroll
            for (int cc = 0; cc < 4; ++cc) {
                float4 xv = *(const float4*)(xs + (c + cc) * LDX + p0);
                float f0 = (&a0.x)[cc], f1 = (&a1.x)[cc];
                float f2 = (&a2.x)[cc], f3 = (&a3.x)[cc];
                acc[0][0] += f0 * xv.x; acc[0][1] += f0 * xv.y; acc[0][2] += f0 * xv.z; acc[0][3] += f0 * xv.w;
                acc[1][0] += f1 * xv.x; acc[1][1] += f1 * xv.y; acc[1][2] += f1 * xv.z; acc[1][3] += f1 * xv.w;
                acc[2][0] += f2 * xv.x; acc[2][1] += f2 * xv.y; acc[2][2] += f2 * xv.z; acc[2][3] += f2 * xv.w;
                acc[3][0] += f3 * xv.x; acc[3][1] += f3 * xv.y; acc[3][2] += f3 * xv.z; acc[3][3] += f3 * xv.w;
            }
        }
        float bb[4] = { bq[ty], bq[ty + 16], bk[ty], bk[ty + 16] };
        #pragma unroll
        for (int r = 0; r < 4; ++r) {
            float4 o = make_float4(acc[r][0] + bb[r], acc[r][1] + bb[r],
                                   acc[r][2] + bb[r], acc[r][3] + bb[r]);
            *(float4*)(qk + (ty + r * 16) * LDP + p0) = o;
        }
    }
    __syncthreads();

    // ---------------- Phase 2: logits + softmax -> at[i][j] ----------------
    // thread (i = t>>2, j-group = t&3 of 16); row reduction via shfl over 4 lanes
    {
        const int i  = t >> 2;
        const int j0 = (t & 3) << 4;
        float acc[16];
        #pragma unroll
        for (int m = 0; m < 16; ++m) acc[m] = 0.f;

        for (int o = 0; o < 32; ++o) {
            float qv = qk[o * LDP + i];
            const float* kr = qk + (32 + o) * LDP + j0;
            #pragma unroll
            for (int m = 0; m < 4; ++m) {
                float4 kv = *(const float4*)(kr + (m << 2));
                acc[4 * m + 0] += qv * kv.x;
                acc[4 * m + 1] += qv * kv.y;
                acc[4 * m + 2] += qv * kv.z;
                acc[4 * m + 3] += qv * kv.w;
            }
        }
        float mx = acc[0];
        #pragma unroll
        for (int m = 1; m < 16; ++m) mx = fmaxf(mx, acc[m]);
        mx = fmaxf(mx, __shfl_xor_sync(0xffffffffu, mx, 1));
        mx = fmaxf(mx, __shfl_xor_sync(0xffffffffu, mx, 2));
        float s = 0.f;
        #pragma unroll
        for (int m = 0; m < 16; ++m) { acc[m] = __expf(acc[m] - mx); s += acc[m]; }
        s += __shfl_xor_sync(0xffffffffu, s, 1);
        s += __shfl_xor_sync(0xffffffffu, s, 2);
        float inv = 1.0f / s;
        #pragma unroll
        for (int m = 0; m < 4; ++m) {
            float4 o = make_float4(acc[4 * m] * inv, acc[4 * m + 1] * inv,
                                   acc[4 * m + 2] * inv, acc[4 * m + 3] * inv);
            *(float4*)(at + i * LDP + j0 + (m << 2)) = o;
        }
    }
    __syncthreads();

    // ---------------- Phase 3: y[e][i] = sum_j xs[e][j] * at[i][j] ---------
    // f32x2 paired over j (both operands are contiguous 8B smem loads).
    // thread: e = r*32 + (t>>3), i = (sh*4+s)*8 + (t&7); two i-halves to cap regs.
    {
        const int eg = t >> 3;
        const int ig = t & 7;
        #pragma unroll
        for (int sh = 0; sh < 2; ++sh) {
            unsigned long long acc2[8][4];
            #pragma unroll
            for (int r = 0; r < 8; ++r)
                #pragma unroll
                for (int s = 0; s < 4; ++s) acc2[r][s] = 0ull;

            for (int j = 0; j < 64; j += 2) {
                unsigned long long xv[8], av[4];
                #pragma unroll
                for (int r = 0; r < 8; ++r)
                    xv[r] = *(const unsigned long long*)(xs + (r * 32 + eg) * LDX + j);
                #pragma unroll
                for (int s = 0; s < 4; ++s)
                    av[s] = *(const unsigned long long*)(at + ((sh * 4 + s) * 8 + ig) * LDP + j);
                #pragma unroll
                for (int r = 0; r < 8; ++r)
                    #pragma unroll
                    for (int s = 0; s < 4; ++s)
                        fma2(acc2[r][s], xv[r], av[s]);
            }
            #pragma unroll
            for (int r = 0; r < 8; ++r)
                #pragma unroll
                for (int s = 0; s < 4; ++s) {
                    float lo, hv; upk2(acc2[r][s], lo, hv);
                    ys[(r * 32 + eg) * LDX + (sh * 4 + s) * 8 + ig] = lo + hv;
                }
        }
    }
    __syncthreads();

    // ---------------- Phase 4: out = Wv @ y + bv, gamma, residual, store ---
    // f32x2 paired over i. thread: c = r*32 + (t>>3), i in [ (t&7)*8, +8 )
    {
        const int cg = t >> 3;
        const int ig = t & 7;
        const int i0 = ig << 3;
        unsigned long long acc2[8][4];
        #pragma unroll
        for (int r = 0; r < 8; ++r)
            #pragma unroll
            for (int s = 0; s < 4; ++s) acc2[r][s] = 0ull;

        for (int e = 0; e < Cc; e += 2) {
            float2 w2r[8];
            #pragma unroll
            for (int r = 0; r < 8; ++r)
                w2r[r] = *(const float2*)(Wv + (size_t)(r * 32 + cg) * Cc + e);
            // ee = 0
            {
                unsigned long long y2[4];
                #pragma unroll
                for (int s = 0; s < 4; ++s)
                    y2[s] = *(const unsigned long long*)(ys + e * LDX + i0 + 2 * s);
                #pragma unroll
                for (int r = 0; r < 8; ++r) {
                    unsigned long long wp = pk2(w2r[r].x, w2r[r].x);
                    #pragma unroll
                    for (int s = 0; s < 4; ++s) fma2(acc2[r][s], wp, y2[s]);
                }
            }
            // ee = 1
            {
                unsigned long long y2[4];
                #pragma unroll
                for (int s = 0; s < 4; ++s)
                    y2[s] = *(const unsigned long long*)(ys + (e + 1) * LDX + i0 + 2 * s);
                #pragma unroll
                for (int r = 0; r < 8; ++r) {
                    unsigned long long wp = pk2(w2r[r].y, w2r[r].y);
                    #pragma unroll
                    for (int s = 0; s < 4; ++s) fma2(acc2[r][s], wp, y2[s]);
                }
            }
        }

        const float g = gamma[0];
        float* ob = out + (size_t)bi * Cc * Hh * Ww;
        const int gy = hi * Aa + ig;   // iy of positions i0..i0+7 is ig
        #pragma unroll
        for (int r = 0; r < 8; ++r) {
            int c = r * 32 + cg;
            float bvv = bv[c];
            #pragma unroll
            for (int s = 0; s < 4; ++s) {
                int ix = 2 * s;
                int gx = wi * Aa + ix;
                if (gy < Hh && gx + 1 < Ww) {
                    float lo, hv; upk2(acc2[r][s], lo, hv);
                    float2 st;
                    st.x = g * (lo + bvv) + xs[c * LDX + i0 + ix];
                    st.y = g * (hv + bvv) + xs[c * LDX + i0 + ix + 1];
                    *(float2*)(ob + ((size_t)c * Hh + gy) * Ww + gx) = st;
                }
            }
        }
    }
}

extern "C" void kernel_launch(void* const* d_in, const int* in_sizes, int n_in,
                              void* d_out, int out_size) {
    (void)in_sizes; (void)n_in; (void)out_size;
    const float* x     = (const float*)d_in[0];
    const float* Wq    = (const float*)d_in[1];
    const float* bq    = (const float*)d_in[2];
    const float* Wk    = (const float*)d_in[3];
    const float* bk    = (const float*)d_in[4];
    const float* Wv    = (const float*)d_in[5];
    const float* bv    = (const float*)d_in[6];
    const float* gamma = (const float*)d_in[7];
    float* out = (float*)d_out;

    size_t smem = (size_t)SMEM_FLOATS * sizeof(float);   // 174,080 B
    cudaFuncSetAttribute(area_attn_kernel,
                         cudaFuncAttributeMaxDynamicSharedMemorySize, (int)smem);
    area_attn_kernel<<<4096, 256, smem>>>(x, Wq, bq, Wk, bk, Wv, bv, gamma, out);
}

// round 2
// speedup vs baseline: 2.3142x; 2.3142x over previous
#include <cuda_runtime.h>
#include <cuda_fp16.h>

// AreaSelfAttention fused kernel, round 2:
//   phases 1-2 (q/k conv + logits + softmax) exact fp32
//   phases 3-4 (y = Xw @ attn^T, out = Wv @ y) on tensor cores (fp16 in, fp32 acc)
// out = gamma * (Wv @ (Xw @ attn^T) + bv) + x   (softmax rows sum to 1 folds v-conv)

#define Cc   256
#define Hh   252
#define Ww   252
#define Aa   8
#define LDX  68     // xs row stride (floats)
#define LDP  68     // qk row stride (floats)
#define LDH  72     // Xh / ath row stride (halves)
#define LDY  264    // ysT row stride (halves): 264*2/4 = 132 banks ≡ 4 (mod 32) -> conflict-free b-frags

// smem byte offsets
#define OFF_XS   0
#define OFF_QK   (OFF_XS  + Cc * LDX * 4)      //  69632
#define OFF_ATH  (OFF_QK  + 64 * LDP * 4)      //  87040
#define OFF_XH   (OFF_ATH + 64 * LDH * 2)      //  96256
#define OFF_YST  (OFF_XH  + Cc * LDH * 2)      // 133120
#define SMEM_BYTES (OFF_YST + 64 * LDY * 2)    // 166912

__device__ __half Wv_h_g[Cc * Cc];

__global__ void wv_prep(const float* __restrict__ Wv) {
    int i = blockIdx.x * 256 + threadIdx.x;    // grid = 256 blocks
    Wv_h_g[i] = __float2half(Wv[i]);
}

static __device__ __forceinline__ void mma16816(float* d, const unsigned* a,
                                                unsigned b0, unsigned b1) {
    asm volatile(
        "mma.sync.aligned.m16n8k16.row.col.f32.f16.f16.f32 "
        "{%0,%1,%2,%3}, {%4,%5,%6,%7}, {%8,%9}, {%0,%1,%2,%3};"
        : "+f"(d[0]), "+f"(d[1]), "+f"(d[2]), "+f"(d[3])
        : "r"(a[0]), "r"(a[1]), "r"(a[2]), "r"(a[3]), "r"(b0), "r"(b1));
}

__global__ __launch_bounds__(256, 1)
void area_attn_kernel(const float* __restrict__ x,
                      const float* __restrict__ Wq, const float* __restrict__ bq,
                      const float* __restrict__ Wk, const float* __restrict__ bk,
                      const float* __restrict__ bv,
                      const float* __restrict__ gamma,
                      float* __restrict__ out)
{
    extern __shared__ char smraw[];
    float*  xs  = (float*) (smraw + OFF_XS);   // [256][LDX] fp32 window (residual + phase1)
    float*  qk  = (float*) (smraw + OFF_QK);   // [64][LDP]  q rows 0..31, k rows 32..63
    __half* ath = (__half*)(smraw + OFF_ATH);  // [64][LDH]  attn fp16 (row i, col j)
    __half* Xh  = (__half*)(smraw + OFF_XH);   // [256][LDH] window fp16 (row c, col pos)
    __half* ysT = (__half*)(smraw + OFF_YST);  // [64][LDY]  y^T fp16 (row i, col e)

    const int t   = threadIdx.x;
    const int blk = blockIdx.x;
    const int bi  = blk >> 10;                 // 4096 = 4 * 32 * 32
    const int hi  = (blk >> 5) & 31;
    const int wi  = blk & 31;

    const float* xb = x + (size_t)bi * Cc * Hh * Ww;

    // ---------------- Phase 0: load x window (fp32 + fp16 copies) ----------
    #pragma unroll
    for (int it = 0; it < 16; ++it) {
        int idx4 = t + (it << 8);
        int c    = idx4 >> 4;
        int rem  = idx4 & 15;
        int iy   = rem >> 1;
        int ix4  = (rem & 1) << 2;
        int gy   = hi * Aa + iy;
        int gx   = wi * Aa + ix4;
        float4 v = make_float4(0.f, 0.f, 0.f, 0.f);
        if (gy < Hh && gx + 3 < Ww)
            v = *(const float4*)(xb + ((size_t)c * Hh + gy) * Ww + gx);
        *(float4*)(xs + c * LDX + (rem << 2)) = v;
        __half2* hp = (__half2*)(Xh + c * LDH + (rem << 2));
        hp[0] = __floats2half2_rn(v.x, v.y);
        hp[1] = __floats2half2_rn(v.z, v.w);
    }
    __syncthreads();

    // ---------------- Phase 1: qk[64][64] = [Wq;Wk] @ Xw + bias (fp32) -----
    {
        const int ty = t >> 4;
        const int p0 = (t & 15) << 2;
        const float* w0 = Wq + ty * Cc;
        const float* w1 = Wq + (ty + 16) * Cc;
        const float* w2 = Wk + ty * Cc;
        const float* w3 = Wk + (ty + 16) * Cc;
        float acc[4][4];
        #pragma unroll
        for (int r = 0; r < 4; ++r)
            #pragma unroll
            for (int s = 0; s < 4; ++s) acc[r][s] = 0.f;

        for (int c = 0; c < Cc; c += 4) {
            float4 a0 = *(const float4*)(w0 + c);
            float4 a1 = *(const float4*)(w1 + c);
            float4 a2 = *(const float4*)(w2 + c);
            float4 a3 = *(const float4*)(w3 + c);
            #pragma unroll
            for (int cc = 0; cc < 4; ++cc) {
                float4 xv = *(const float4*)(xs + (c + cc) * LDX + p0);
                float f0 = (&a0.x)[cc], f1 = (&a1.x)[cc];
                float f2 = (&a2.x)[cc], f3 = (&a3.x)[cc];
                acc[0][0] += f0 * xv.x; acc[0][1] += f0 * xv.y; acc[0][2] += f0 * xv.z; acc[0][3] += f0 * xv.w;
                acc[1][0] += f1 * xv.x; acc[1][1] += f1 * xv.y; acc[1][2] += f1 * xv.z; acc[1][3] += f1 * xv.w;
                acc[2][0] += f2 * xv.x; acc[2][1] += f2 * xv.y; acc[2][2] += f2 * xv.z; acc[2][3] += f2 * xv.w;
                acc[3][0] += f3 * xv.x; acc[3][1] += f3 * xv.y; acc[3][2] += f3 * xv.z; acc[3][3] += f3 * xv.w;
            }
        }
        float bb[4] = { bq[ty], bq[ty + 16], bk[ty], bk[ty + 16] };
        #pragma unroll
        for (int r = 0; r < 4; ++r) {
            float4 o = make_float4(acc[r][0] + bb[r], acc[r][1] + bb[r],
                                   acc[r][2] + bb[r], acc[r][3] + bb[r]);
            *(float4*)(qk + (ty + r * 16) * LDP + p0) = o;
        }
    }
    __syncthreads();

    // ---------------- Phase 2: logits + softmax (fp32) -> ath fp16 ---------
    {
        const int i  = t >> 2;
        const int j0 = (t & 3) << 4;
        float acc[16];
        #pragma unroll
        for (int m = 0; m < 16; ++m) acc[m] = 0.f;

        for (int o = 0; o < 32; ++o) {
            float qv = qk[o * LDP + i];
            const float* kr = qk + (32 + o) * LDP + j0;
            #pragma unroll
            for (int m = 0; m < 4; ++m) {
                float4 kv = *(const float4*)(kr + (m << 2));
                acc[4 * m + 0] += qv * kv.x;
                acc[4 * m + 1] += qv * kv.y;
                acc[4 * m + 2] += qv * kv.z;
                acc[4 * m + 3] += qv * kv.w;
            }
        }
        float mx = acc[0];
        #pragma unroll
        for (int m = 1; m < 16; ++m) mx = fmaxf(mx, acc[m]);
        mx = fmaxf(mx, __shfl_xor_sync(0xffffffffu, mx, 1));
        mx = fmaxf(mx, __shfl_xor_sync(0xffffffffu, mx, 2));
        float s = 0.f;
        #pragma unroll
        for (int m = 0; m < 16; ++m) { acc[m] = __expf(acc[m] - mx); s += acc[m]; }
        s += __shfl_xor_sync(0xffffffffu, s, 1);
        s += __shfl_xor_sync(0xffffffffu, s, 2);
        float inv = 1.0f / s;
        #pragma unroll
        for (int m = 0; m < 4; ++m) {
            __half2* hp = (__half2*)(ath + i * LDH + j0 + (m << 2));
            hp[0] = __floats2half2_rn(acc[4 * m + 0] * inv, acc[4 * m + 1] * inv);
            hp[1] = __floats2half2_rn(acc[4 * m + 2] * inv, acc[4 * m + 3] * inv);
        }
    }
    __syncthreads();

    const int w    = t >> 5;
    const int lane = t & 31;
    const int gid  = lane >> 2;
    const int tg   = lane & 3;

    // ---------------- Phase 3: y = Xw @ attn^T via MMA; store ysT[i][e] ----
    // warp w: e-strip [32w, 32w+32) (2 m16 tiles), all 64 i (8 n8 tiles), K=64
    {
        float d[2][8][4];
        #pragma unroll
        for (int mt = 0; mt < 2; ++mt)
            #pragma unroll
            for (int nt = 0; nt < 8; ++nt)
                #pragma unroll
                for (int r = 0; r < 4; ++r) d[mt][nt][r] = 0.f;

        #pragma unroll
        for (int ks = 0; ks < 4; ++ks) {
            const int j0 = ks * 16 + 2 * tg;
            unsigned a[2][4];
            #pragma unroll
            for (int mt = 0; mt < 2; ++mt) {
                const __half* base = Xh + (w * 32 + mt * 16 + gid) * LDH + j0;
                a[mt][0] = *(const unsigned*)(base);
                a[mt][1] = *(const unsigned*)(base + 8 * LDH);
                a[mt][2] = *(const unsigned*)(base + 8);
                a[mt][3] = *(const unsigned*)(base + 8 * LDH + 8);
            }
            #pragma unroll
            for (int nt = 0; nt < 8; ++nt) {
                const __half* bb = ath + (nt * 8 + gid) * LDH + j0;
                unsigned b0 = *(const unsigned*)(bb);
                unsigned b1 = *(const unsigned*)(bb + 8);
                mma16816(d[0][nt], a[0], b0, b1);
                mma16816(d[1][nt], a[1], b0, b1);
            }
        }
        #pragma unroll
        for (int mt = 0; mt < 2; ++mt) {
            int e = w * 32 + mt * 16 + gid;
            #pragma unroll
            for (int nt = 0; nt < 8; ++nt) {
                int i = nt * 8 + 2 * tg;
                ysT[ i      * LDY + e    ] = __float2half(d[mt][nt][0]);
                ysT[(i + 1) * LDY + e    ] = __float2half(d[mt][nt][1]);
                ysT[ i      * LDY + e + 8] = __float2half(d[mt][nt][2]);
                ysT[(i + 1) * LDY + e + 8] = __float2half(d[mt][nt][3]);
            }
        }
    }
    __syncthreads();

    // ---------------- Phase 4: out = Wv @ y via MMA + epilogue -------------
    // warp w: c-strip [32w, 32w+32), all 64 i, K=256. A-frags from global fp16 Wv.
    {
        float d[2][8][4];
        #pragma unroll
        for (int mt = 0; mt < 2; ++mt)
            #pragma unroll
            for (int nt = 0; nt < 8; ++nt)
                #pragma unroll
                for (int r = 0; r < 4; ++r) d[mt][nt][r] = 0.f;

        const __half* W0 = Wv_h_g + (w * 32 + gid) * Cc + 2 * tg;
        #pragma unroll
        for (int ks = 0; ks < 16; ++ks) {
            const int e0 = ks * 16;
            unsigned a[2][4];
            #pragma unroll
            for (int mt = 0; mt < 2; ++mt) {
                const __half* base = W0 + mt * 16 * Cc + e0;
                a[mt][0] = *(const unsigned*)(base);
                a[mt][1] = *(const unsigned*)(base + 8 * Cc);
                a[mt][2] = *(const unsigned*)(base + 8);
                a[mt][3] = *(const unsigned*)(base + 8 * Cc + 8);
            }
            #pragma unroll
            for (int nt = 0; nt < 8; ++nt) {
                const __half* bb = ysT + (nt * 8 + gid) * LDY + e0 + 2 * tg;
                unsigned b0 = *(const unsigned*)(bb);
                unsigned b1 = *(const unsigned*)(bb + 8);
                mma16816(d[0][nt], a[0], b0, b1);
                mma16816(d[1][nt], a[1], b0, b1);
            }
        }

        const float g = gamma[0];
        float* ob = out + (size_t)bi * Cc * Hh * Ww;
        #pragma unroll
        for (int mt = 0; mt < 2; ++mt) {
            int cA = w * 32 + mt * 16 + gid;
            int cB = cA + 8;
            float bvA = bv[cA], bvB = bv[cB];
            #pragma unroll
            for (int nt = 0; nt < 8; ++nt) {
                int gy = hi * Aa + nt;           // i = nt*8 + 2tg -> iy = nt
                int gx = wi * Aa + 2 * tg;
                if (gy < Hh && gx + 1 < Ww) {
                    int i = nt * 8 + 2 * tg;
                    float2 rA = *(const float2*)(xs + cA * LDX + i);
                    float2 rB = *(const float2*)(xs + cB * LDX + i);
                    float2 sA, sB;
                    sA.x = g * (d[mt][nt][0] + bvA) + rA.x;
                    sA.y = g * (d[mt][nt][1] + bvA) + rA.y;
                    sB.x = g * (d[mt][nt][2] + bvB) + rB.x;
                    sB.y = g * (d[mt][nt][3] + bvB) + rB.y;
                    *(float2*)(ob + ((size_t)cA * Hh + gy) * Ww + gx) = sA;
                    *(float2*)(ob + ((size_t)cB * Hh + gy) * Ww + gx) = sB;
                }
            }
        }
    }
}

extern "C" void kernel_launch(void* const* d_in, const int* in_sizes, int n_in,
                              void* d_out, int out_size) {
    (void)in_sizes; (void)n_in; (void)out_size;
    const float* x     = (const float*)d_in[0];
    const float* Wq    = (const float*)d_in[1];
    const float* bq    = (const float*)d_in[2];
    const float* Wk    = (const float*)d_in[3];
    const float* bk    = (const float*)d_in[4];
    const float* Wv    = (const float*)d_in[5];
    const float* bv    = (const float*)d_in[6];
    const float* gamma = (const float*)d_in[7];
    float* out = (float*)d_out;

    cudaFuncSetAttribute(area_attn_kernel,
                         cudaFuncAttributeMaxDynamicSharedMemorySize, SMEM_BYTES);

    wv_prep<<<256, 256>>>(Wv);
    area_attn_kernel<<<4096, 256, SMEM_BYTES>>>(x, Wq, bq, Wk, bk, bv, gamma, out);
}

// round 3
// speedup vs baseline: 4.3033x; 1.8595x over previous
#include <cuda_runtime.h>
#include <cuda_fp16.h>

// AreaSelfAttention fused kernel, round 3:
//   phase 1 (q/k conv), phase 3 (y = Xw @ attn^T), phase 4 (Wv @ y) on tensor cores
//   phase 2 (logits + softmax) exact fp32
// out = gamma * (Wv @ (Xw @ attn^T) + bv) + x   (softmax rows sum to 1 folds v-conv)

#define Cc   256
#define Hh   252
#define Ww   252
#define Aa   8
#define LDX  68     // xs row stride (floats)
#define LDP  68     // qk row stride (floats)
#define LDH  72     // Xh / ath row stride (halves) -> 144B rows, ldmatrix conflict-free
#define LDY  264    // ysT row stride (halves) -> 528B rows, ldmatrix conflict-free

// smem byte offsets
#define OFF_XS   0
#define OFF_QK   (OFF_XS  + Cc * LDX * 4)      //  69632
#define OFF_ATH  (OFF_QK  + 64 * LDP * 4)      //  87040
#define OFF_XH   (OFF_ATH + 64 * LDH * 2)      //  96256
#define OFF_YST  (OFF_XH  + Cc * LDH * 2)      // 133120
#define SMEM_BYTES (OFF_YST + 64 * LDY * 2)    // 166912

// Fragment-packed fp16 weights (prep kernel fills these once per launch).
// Layout: [mtile][ks][lane][4 regs] of b32; reg r = A[gid + 8*(r&1)][ks*16 + 2*tg + 8*(r>>1)]
__device__ uint4 Wqk_pk4[4 * 16 * 32];     // [Wq;Wk] 64x256
__device__ uint4 Wv_pk4[16 * 16 * 32];     // Wv 256x256

__global__ void prep_pack(const float* __restrict__ Wq,
                          const float* __restrict__ Wk,
                          const float* __restrict__ Wv) {
    int u = blockIdx.x * 256 + threadIdx.x;      // grid 160 -> 40960 b32 outputs
    if (u < 8192) {
        int r = u & 3, lane = (u >> 2) & 31, ks = (u >> 7) & 15, mt = u >> 11;
        int gid = lane >> 2, tg = lane & 3;
        int row = mt * 16 + gid + 8 * (r & 1);
        int col = ks * 16 + 2 * tg + 8 * (r >> 1);
        const float* src = (row < 32) ? (Wq + row * Cc) : (Wk + (row - 32) * Cc);
        __half2 h = __floats2half2_rn(src[col], src[col + 1]);
        ((unsigned*)Wqk_pk4)[u] = *(unsigned*)&h;
    } else {
        int v = u - 8192;
        int r = v & 3, lane = (v >> 2) & 31, ks = (v >> 7) & 15, mt = v >> 11;
        int gid = lane >> 2, tg = lane & 3;
        int row = mt * 16 + gid + 8 * (r & 1);
        int col = ks * 16 + 2 * tg + 8 * (r >> 1);
        const float* src = Wv + (size_t)row * Cc;
        __half2 h = __floats2half2_rn(src[col], src[col + 1]);
        ((unsigned*)Wv_pk4)[v] = *(unsigned*)&h;
    }
}

static __device__ __forceinline__ void mma16816(float* d, const unsigned* a,
                                                unsigned b0, unsigned b1) {
    asm volatile(
        "mma.sync.aligned.m16n8k16.row.col.f32.f16.f16.f32 "
        "{%0,%1,%2,%3}, {%4,%5,%6,%7}, {%8,%9}, {%0,%1,%2,%3};"
        : "+f"(d[0]), "+f"(d[1]), "+f"(d[2]), "+f"(d[3])
        : "r"(a[0]), "r"(a[1]), "r"(a[2]), "r"(a[3]), "r"(b0), "r"(b1));
}
static __device__ __forceinline__ unsigned cvsm(const void* p) {
    return (unsigned)__cvta_generic_to_shared(p);
}
static __device__ __forceinline__ void ldsm_x2(unsigned& r0, unsigned& r1, unsigned a) {
    asm volatile("ldmatrix.sync.aligned.m8n8.x2.shared.b16 {%0,%1}, [%2];"
                 : "=r"(r0), "=r"(r1) : "r"(a));
}
static __device__ __forceinline__ void ldsm_x2t(unsigned& r0, unsigned& r1, unsigned a) {
    asm volatile("ldmatrix.sync.aligned.m8n8.x2.trans.shared.b16 {%0,%1}, [%2];"
                 : "=r"(r0), "=r"(r1) : "r"(a));
}
static __device__ __forceinline__ void ldsm_x4(unsigned* r, unsigned a) {
    asm volatile("ldmatrix.sync.aligned.m8n8.x4.shared.b16 {%0,%1,%2,%3}, [%4];"
                 : "=r"(r[0]), "=r"(r[1]), "=r"(r[2]), "=r"(r[3]) : "r"(a));
}

__global__ __launch_bounds__(256, 1)
void area_attn_kernel(const float* __restrict__ x,
                      const float* __restrict__ bq, const float* __restrict__ bk,
                      const float* __restrict__ bv,
                      const float* __restrict__ gamma,
                      float* __restrict__ out)
{
    extern __shared__ char smraw[];
    float*  xs  = (float*) (smraw + OFF_XS);   // [256][LDX] fp32 window (residual)
    float*  qk  = (float*) (smraw + OFF_QK);   // [64][LDP]  q rows 0..31, k rows 32..63 (fp32)
    __half* ath = (__half*)(smraw + OFF_ATH);  // [64][LDH]  attn fp16 (row i, col j)
    __half* Xh  = (__half*)(smraw + OFF_XH);   // [256][LDH] window fp16 (row c, col pos)
    __half* ysT = (__half*)(smraw + OFF_YST);  // [64][LDY]  y^T fp16 (row i, col e)

    const int t   = threadIdx.x;
    const int blk = blockIdx.x;
    const int bi  = blk >> 10;                 // 4096 = 4 * 32 * 32
    const int hi  = (blk >> 5) & 31;
    const int wi  = blk & 31;

    const float* xb = x + (size_t)bi * Cc * Hh * Ww;

    // ---------------- Phase 0: load x window (fp32 + fp16 copies) ----------
    #pragma unroll
    for (int it = 0; it < 16; ++it) {
        int idx4 = t + (it << 8);
        int c    = idx4 >> 4;
        int rem  = idx4 & 15;
        int iy   = rem >> 1;
        int ix4  = (rem & 1) << 2;
        int gy   = hi * Aa + iy;
        int gx   = wi * Aa + ix4;
        float4 v = make_float4(0.f, 0.f, 0.f, 0.f);
        if (gy < Hh && gx + 3 < Ww)
            v = *(const float4*)(xb + ((size_t)c * Hh + gy) * Ww + gx);
        *(float4*)(xs + c * LDX + (rem << 2)) = v;
        __half2* hp = (__half2*)(Xh + c * LDH + (rem << 2));
        hp[0] = __floats2half2_rn(v.x, v.y);
        hp[1] = __floats2half2_rn(v.z, v.w);
    }
    __syncthreads();

    const int w    = t >> 5;
    const int lane = t & 31;
    const int gid  = lane >> 2;
    const int tg   = lane & 3;

    // ---------------- Phase 1: qk = [Wq;Wk] @ Xw + bias via MMA ------------
    // warp w: m-tile (w&3) of 4, n-half (w>>2): 32 positions, K=256.
    {
        const int mt1   = w & 3;
        const int nbase = (w >> 2) * 32;
        float d[4][4];
        #pragma unroll
        for (int nt = 0; nt < 4; ++nt)
            #pragma unroll
            for (int r = 0; r < 4; ++r) d[nt][r] = 0.f;

        #pragma unroll
        for (int ks = 0; ks < 16; ++ks) {
            uint4 av = Wqk_pk4[(mt1 * 16 + ks) * 32 + lane];
            unsigned baddr = cvsm(Xh + (ks * 16 + (lane & 15)) * LDH + nbase);
            #pragma unroll
            for (int nt = 0; nt < 4; ++nt) {
                unsigned b0, b1;
                ldsm_x2t(b0, b1, baddr + nt * 16);   // +8 halves per n-tile
                mma16816(d[nt], (const unsigned*)&av, b0, b1);
            }
        }
        const int oc0 = mt1 * 16 + gid;
        const int oc1 = oc0 + 8;
        float bb0 = (mt1 < 2) ? bq[oc0] : bk[oc0 - 32];
        float bb1 = (mt1 < 2) ? bq[oc1] : bk[oc1 - 32];
        #pragma unroll
        for (int nt = 0; nt < 4; ++nt) {
            int pos = nbase + nt * 8 + 2 * tg;
            *(float2*)(qk + oc0 * LDP + pos) = make_float2(d[nt][0] + bb0, d[nt][1] + bb0);
            *(float2*)(qk + oc1 * LDP + pos) = make_float2(d[nt][2] + bb1, d[nt][3] + bb1);
        }
    }
    __syncthreads();

    // ---------------- Phase 2: logits + softmax (fp32) -> ath fp16 ---------
    {
        const int i  = t >> 2;
        const int j0 = (t & 3) << 4;
        float acc[16];
        #pragma unroll
        for (int m = 0; m < 16; ++m) acc[m] = 0.f;

        for (int o = 0; o < 32; ++o) {
            float qv = qk[o * LDP + i];
            const float* kr = qk + (32 + o) * LDP + j0;
            #pragma unroll
            for (int m = 0; m < 4; ++m) {
                float4 kv = *(const float4*)(kr + (m << 2));
                acc[4 * m + 0] += qv * kv.x;
                acc[4 * m + 1] += qv * kv.y;
                acc[4 * m + 2] += qv * kv.z;
                acc[4 * m + 3] += qv * kv.w;
            }
        }
        float mx = acc[0];
        #pragma unroll
        for (int m = 1; m < 16; ++m) mx = fmaxf(mx, acc[m]);
        mx = fmaxf(mx, __shfl_xor_sync(0xffffffffu, mx, 1));
        mx = fmaxf(mx, __shfl_xor_sync(0xffffffffu, mx, 2));
        float s = 0.f;
        #pragma unroll
        for (int m = 0; m < 16; ++m) { acc[m] = __expf(acc[m] - mx); s += acc[m]; }
        s += __shfl_xor_sync(0xffffffffu, s, 1);
        s += __shfl_xor_sync(0xffffffffu, s, 2);
        float inv = 1.0f / s;
        #pragma unroll
        for (int m = 0; m < 4; ++m) {
            __half2* hp = (__half2*)(ath + i * LDH + j0 + (m << 2));
            hp[0] = __floats2half2_rn(acc[4 * m + 0] * inv, acc[4 * m + 1] * inv);
            hp[1] = __floats2half2_rn(acc[4 * m + 2] * inv, acc[4 * m + 3] * inv);
        }
    }
    __syncthreads();

    // ---------------- Phase 3: y = Xw @ attn^T via MMA; store ysT[i][e] ----
    // warp w: e-strip [32w, 32w+32), all 64 i, K=64.
    {
        float d[2][8][4];
        #pragma unroll
        for (int mt = 0; mt < 2; ++mt)
            #pragma unroll
            for (int nt = 0; nt < 8; ++nt)
                #pragma unroll
                for (int r = 0; r < 4; ++r) d[mt][nt][r] = 0.f;

        const int q4   = lane >> 3;            // ldmatrix x4 lane group
        const int row8 = lane & 7;

        #pragma unroll
        for (int ks = 0; ks < 4; ++ks) {
            const int j0 = ks * 16;
            unsigned a[2][4];
            #pragma unroll
            for (int mt = 0; mt < 2; ++mt) {
                unsigned addr = cvsm(Xh + (w * 32 + mt * 16 + (q4 & 1) * 8 + row8) * LDH
                                        + j0 + (q4 >> 1) * 8);
                ldsm_x4(a[mt], addr);
            }
            #pragma unroll
            for (int nt = 0; nt < 8; ++nt) {
                unsigned baddr = cvsm(ath + (nt * 8 + row8) * LDH + j0 + (q4 & 1) * 8);
                unsigned b0, b1;
                ldsm_x2(b0, b1, baddr);
                mma16816(d[0][nt], a[0], b0, b1);
                mma16816(d[1][nt], a[1], b0, b1);
            }
        }
        #pragma unroll
        for (int mt = 0; mt < 2; ++mt) {
            int e = w * 32 + mt * 16 + gid;
            #pragma unroll
            for (int nt = 0; nt < 8; ++nt) {
                int i = nt * 8 + 2 * tg;
                ysT[ i      * LDY + e    ] = __float2half(d[mt][nt][0]);
                ysT[(i + 1) * LDY + e    ] = __float2half(d[mt][nt][1]);
                ysT[ i      * LDY + e + 8] = __float2half(d[mt][nt][2]);
                ysT[(i + 1) * LDY + e + 8] = __float2half(d[mt][nt][3]);
            }
        }
    }
    __syncthreads();

    // ---------------- Phase 4: out = Wv @ y via MMA + epilogue -------------
    // warp w: c-strip [32w, 32w+32), all 64 i, K=256. A from packed global Wv.
    {
        float d[2][8][4];
        #pragma unroll
        for (int mt = 0; mt < 2; ++mt)
            #pragma unroll
            for (int nt = 0; nt < 8; ++nt)
                #pragma unroll
                for (int r = 0; r < 4; ++r) d[mt][nt][r] = 0.f;

        const int q4   = lane >> 3;
        const int row8 = lane & 7;

        #pragma unroll
        for (int ks = 0; ks < 16; ++ks) {
            uint4 av0 = Wv_pk4[((w * 2 + 0) * 16 + ks) * 32 + lane];
            uint4 av1 = Wv_pk4[((w * 2 + 1) * 16 + ks) * 32 + lane];
            const int e0 = ks * 16;
            #pragma unroll
            for (int nt = 0; nt < 8; ++nt) {
                unsigned baddr = cvsm(ysT + (nt * 8 + row8) * LDY + e0 + (q4 & 1) * 8);
                unsigned b0, b1;
                ldsm_x2(b0, b1, baddr);
                mma16816(d[0][nt], (const unsigned*)&av0, b0, b1);
                mma16816(d[1][nt], (const unsigned*)&av1, b0, b1);
            }
        }

        const float g = gamma[0];
        float* ob = out + (size_t)bi * Cc * Hh * Ww;
        #pragma unroll
        for (int mt = 0; mt < 2; ++mt) {
            int cA = w * 32 + mt * 16 + gid;
            int cB = cA + 8;
            float bvA = bv[cA], bvB = bv[cB];
            #pragma unroll
            for (int nt = 0; nt < 8; ++nt) {
                int gy = hi * Aa + nt;           // i = nt*8 + 2tg -> iy = nt
                int gx = wi * Aa + 2 * tg;
                if (gy < Hh && gx + 1 < Ww) {
                    int i = nt * 8 + 2 * tg;
                    float2 rA = *(const float2*)(xs + cA * LDX + i);
                    float2 rB = *(const float2*)(xs + cB * LDX + i);
                    float2 sA, sB;
                    sA.x = g * (d[mt][nt][0] + bvA) + rA.x;
                    sA.y = g * (d[mt][nt][1] + bvA) + rA.y;
                    sB.x = g * (d[mt][nt][2] + bvB) + rB.x;
                    sB.y = g * (d[mt][nt][3] + bvB) + rB.y;
                    *(float2*)(ob + ((size_t)cA * Hh + gy) * Ww + gx) = sA;
                    *(float2*)(ob + ((size_t)cB * Hh + gy) * Ww + gx) = sB;
                }
            }
        }
    }
}

extern "C" void kernel_launch(void* const* d_in, const int* in_sizes, int n_in,
                              void* d_out, int out_size) {
    (void)in_sizes; (void)n_in; (void)out_size;
    const float* x     = (const float*)d_in[0];
    const float* Wq    = (const float*)d_in[1];
    const float* bq    = (const float*)d_in[2];
    const float* Wk    = (const float*)d_in[3];
    const float* bk    = (const float*)d_in[4];
    const float* Wv    = (const float*)d_in[5];
    const float* bv    = (const float*)d_in[6];
    const float* gamma = (const float*)d_in[7];
    float* out = (float*)d_out;

    cudaFuncSetAttribute(area_attn_kernel,
                         cudaFuncAttributeMaxDynamicSharedMemorySize, SMEM_BYTES);

    prep_pack<<<160, 256>>>(Wq, Wk, Wv);
    area_attn_kernel<<<4096, 256, SMEM_BYTES>>>(x, bq, bk, bv, gamma, out);
}

// round 8
// speedup vs baseline: 4.8606x; 1.1295x over previous
#include <cuda_runtime.h>
#include <cuda_fp16.h>

// AreaSelfAttention fused kernel, round 4:
//   all three GEMMs on tensor cores; softmax exact fp32.
//   smem cut to 97 KB (dropped fp32 window copy) -> 2 CTAs/SM.
//   Residual x re-read from global (L2-hit) in the epilogue.
// out = gamma * (Wv @ (Xw @ attn^T) + bv) + x

#define Cc   256
#define Hh   252
#define Ww   252
#define Aa   8
#define LDP  68     // qk row stride (floats)
#define LDH  72     // Xh / ath row stride (halves) -> 144B rows, ldmatrix conflict-free
#define LDY  264    // ysT row stride (halves) -> 528B rows, ldmatrix conflict-free

// smem byte offsets (total 97280 B -> 2 CTAs/SM)
#define OFF_QK   0
#define OFF_ATH  (OFF_QK  + 64 * LDP * 4)      // 17408
#define OFF_XH   (OFF_ATH + 64 * LDH * 2)      // 26624
#define OFF_YST  (OFF_XH  + Cc * LDH * 2)      // 63488
#define SMEM_BYTES (OFF_YST + 64 * LDY * 2)    // 97280

// Fragment-packed fp16 weights (prep kernel fills once per launch).
// reg r of lane = A[mt*16 + gid + 8*(r&1)][ks*16 + 2*tg + 8*(r>>1)]
__device__ uint4 Wqk_pk4[4 * 16 * 32];     // [Wq;Wk] 64x256
__device__ uint4 Wv_pk4[16 * 16 * 32];     // Wv 256x256

__global__ void prep_pack(const float* __restrict__ Wq,
                          const float* __restrict__ Wk,
                          const float* __restrict__ Wv) {
    int u = blockIdx.x * 256 + threadIdx.x;      // grid 160 -> 40960 b32 outputs
    if (u < 8192) {
        int r = u & 3, lane = (u >> 2) & 31, ks = (u >> 7) & 15, mt = u >> 11;
        int gid = lane >> 2, tg = lane & 3;
        int row = mt * 16 + gid + 8 * (r & 1);
        int col = ks * 16 + 2 * tg + 8 * (r >> 1);
        const float* src = (row < 32) ? (Wq + row * Cc) : (Wk + (row - 32) * Cc);
        __half2 h = __floats2half2_rn(src[col], src[col + 1]);
        ((unsigned*)Wqk_pk4)[u] = *(unsigned*)&h;
    } else {
        int v = u - 8192;
        int r = v & 3, lane = (v >> 2) & 31, ks = (v >> 7) & 15, mt = v >> 11;
        int gid = lane >> 2, tg = lane & 3;
        int row = mt * 16 + gid + 8 * (r & 1);
        int col = ks * 16 + 2 * tg + 8 * (r >> 1);
        const float* src = Wv + (size_t)row * Cc;
        __half2 h = __floats2half2_rn(src[col], src[col + 1]);
        ((unsigned*)Wv_pk4)[v] = *(unsigned*)&h;
    }
}

static __device__ __forceinline__ void mma16816(float* d, const unsigned* a,
                                                unsigned b0, unsigned b1) {
    asm volatile(
        "mma.sync.aligned.m16n8k16.row.col.f32.f16.f16.f32 "
        "{%0,%1,%2,%3}, {%4,%5,%6,%7}, {%8,%9}, {%0,%1,%2,%3};"
        : "+f"(d[0]), "+f"(d[1]), "+f"(d[2]), "+f"(d[3])
        : "r"(a[0]), "r"(a[1]), "r"(a[2]), "r"(a[3]), "r"(b0), "r"(b1));
}
static __device__ __forceinline__ unsigned cvsm(const void* p) {
    return (unsigned)__cvta_generic_to_shared(p);
}
static __device__ __forceinline__ void ldsm_x2(unsigned& r0, unsigned& r1, unsigned a) {
    asm volatile("ldmatrix.sync.aligned.m8n8.x2.shared.b16 {%0,%1}, [%2];"
                 : "=r"(r0), "=r"(r1) : "r"(a));
}
static __device__ __forceinline__ void ldsm_x2t(unsigned& r0, unsigned& r1, unsigned a) {
    asm volatile("ldmatrix.sync.aligned.m8n8.x2.trans.shared.b16 {%0,%1}, [%2];"
                 : "=r"(r0), "=r"(r1) : "r"(a));
}
static __device__ __forceinline__ void ldsm_x4(unsigned* r, unsigned a) {
    asm volatile("ldmatrix.sync.aligned.m8n8.x4.shared.b16 {%0,%1,%2,%3}, [%4];"
                 : "=r"(r[0]), "=r"(r[1]), "=r"(r[2]), "=r"(r[3]) : "r"(a));
}

__global__ __launch_bounds__(256, 2)
void area_attn_kernel(const float* __restrict__ x,
                      const float* __restrict__ bq, const float* __restrict__ bk,
                      const float* __restrict__ bv,
                      const float* __restrict__ gamma,
                      float* __restrict__ out)
{
    extern __shared__ char smraw[];
    float*  qk  = (float*) (smraw + OFF_QK);   // [64][LDP]  q rows 0..31, k rows 32..63 (fp32)
    __half* ath = (__half*)(smraw + OFF_ATH);  // [64][LDH]  attn fp16 (row i, col j)
    __half* Xh  = (__half*)(smraw + OFF_XH);   // [256][LDH] window fp16 (row c, col pos)
    __half* ysT = (__half*)(smraw + OFF_YST);  // [64][LDY]  y^T fp16 (row i, col e)

    const int t   = threadIdx.x;
    const int blk = blockIdx.x;
    const int bi  = blk >> 10;                 // 4096 = 4 * 32 * 32
    const int hi  = (blk >> 5) & 31;
    const int wi  = blk & 31;

    const float* xb = x + (size_t)bi * Cc * Hh * Ww;

    // ---------------- Phase 0: load x window -> Xh (fp16, zero-padded) -----
    #pragma unroll
    for (int it = 0; it < 16; ++it) {
        int idx4 = t + (it << 8);
        int c    = idx4 >> 4;
        int rem  = idx4 & 15;
        int iy   = rem >> 1;
        int ix4  = (rem & 1) << 2;
        int gy   = hi * Aa + iy;
        int gx   = wi * Aa + ix4;
        float4 v = make_float4(0.f, 0.f, 0.f, 0.f);
        if (gy < Hh && gx + 3 < Ww)
            v = *(const float4*)(xb + ((size_t)c * Hh + gy) * Ww + gx);
        __half2* hp = (__half2*)(Xh + c * LDH + (rem << 2));
        hp[0] = __floats2half2_rn(v.x, v.y);
        hp[1] = __floats2half2_rn(v.z, v.w);
    }
    __syncthreads();

    const int w    = t >> 5;
    const int lane = t & 31;
    const int gid  = lane >> 2;
    const int tg   = lane & 3;

    // ---------------- Phase 1: qk = [Wq;Wk] @ Xw + bias via MMA ------------
    // warp w: m-tile (w&3), n-half (w>>2)*32 positions, K=256.
    {
        const int mt1   = w & 3;
        const int nbase = (w >> 2) * 32;
        float d[4][4];
        #pragma unroll
        for (int nt = 0; nt < 4; ++nt)
            #pragma unroll
            for (int r = 0; r < 4; ++r) d[nt][r] = 0.f;

        #pragma unroll
        for (int ks = 0; ks < 16; ++ks) {
            uint4 av = Wqk_pk4[(mt1 * 16 + ks) * 32 + lane];
            unsigned baddr = cvsm(Xh + (ks * 16 + (lane & 15)) * LDH + nbase);
            #pragma unroll
            for (int nt = 0; nt < 4; ++nt) {
                unsigned b0, b1;
                ldsm_x2t(b0, b1, baddr + nt * 16);
                mma16816(d[nt], (const unsigned*)&av, b0, b1);
            }
        }
        const int oc0 = mt1 * 16 + gid;
        const int oc1 = oc0 + 8;
        float bb0 = (mt1 < 2) ? bq[oc0] : bk[oc0 - 32];
        float bb1 = (mt1 < 2) ? bq[oc1] : bk[oc1 - 32];
        #pragma unroll
        for (int nt = 0; nt < 4; ++nt) {
            int pos = nbase + nt * 8 + 2 * tg;
            *(float2*)(qk + oc0 * LDP + pos) = make_float2(d[nt][0] + bb0, d[nt][1] + bb0);
            *(float2*)(qk + oc1 * LDP + pos) = make_float2(d[nt][2] + bb1, d[nt][3] + bb1);
        }
    }
    __syncthreads();

    // ---------------- Phase 2: logits + softmax (fp32) -> ath fp16 ---------
    {
        const int i  = t >> 2;
        const int j0 = (t & 3) << 4;
        float acc[16];
        #pragma unroll
        for (int m = 0; m < 16; ++m) acc[m] = 0.f;

        for (int o = 0; o < 32; ++o) {
            float qv = qk[o * LDP + i];
            const float* kr = qk + (32 + o) * LDP + j0;
            #pragma unroll
            for (int m = 0; m < 4; ++m) {
                float4 kv = *(const float4*)(kr + (m << 2));
                acc[4 * m + 0] += qv * kv.x;
                acc[4 * m + 1] += qv * kv.y;
                acc[4 * m + 2] += qv * kv.z;
                acc[4 * m + 3] += qv * kv.w;
            }
        }
        float mx = acc[0];
        #pragma unroll
        for (int m = 1; m < 16; ++m) mx = fmaxf(mx, acc[m]);
        mx = fmaxf(mx, __shfl_xor_sync(0xffffffffu, mx, 1));
        mx = fmaxf(mx, __shfl_xor_sync(0xffffffffu, mx, 2));
        float s = 0.f;
        #pragma unroll
        for (int m = 0; m < 16; ++m) { acc[m] = __expf(acc[m] - mx); s += acc[m]; }
        s += __shfl_xor_sync(0xffffffffu, s, 1);
        s += __shfl_xor_sync(0xffffffffu, s, 2);
        float inv = 1.0f / s;
        #pragma unroll
        for (int m = 0; m < 4; ++m) {
            __half2* hp = (__half2*)(ath + i * LDH + j0 + (m << 2));
            hp[0] = __floats2half2_rn(acc[4 * m + 0] * inv, acc[4 * m + 1] * inv);
            hp[1] = __floats2half2_rn(acc[4 * m + 2] * inv, acc[4 * m + 3] * inv);
        }
    }
    __syncthreads();

    // ---------------- Phase 3: y = Xw @ attn^T via MMA; store ysT[i][e] ----
    {
        float d[2][8][4];
        #pragma unroll
        for (int mt = 0; mt < 2; ++mt)
            #pragma unroll
            for (int nt = 0; nt < 8; ++nt)
                #pragma unroll
                for (int r = 0; r < 4; ++r) d[mt][nt][r] = 0.f;

        const int q4   = lane >> 3;
        const int row8 = lane & 7;

        #pragma unroll
        for (int ks = 0; ks < 4; ++ks) {
            const int j0 = ks * 16;
            unsigned a[2][4];
            #pragma unroll
            for (int mt = 0; mt < 2; ++mt) {
                unsigned addr = cvsm(Xh + (w * 32 + mt * 16 + (q4 & 1) * 8 + row8) * LDH
                                        + j0 + (q4 >> 1) * 8);
                ldsm_x4(a[mt], addr);
            }
            #pragma unroll
            for (int nt = 0; nt < 8; ++nt) {
                unsigned baddr = cvsm(ath + (nt * 8 + row8) * LDH + j0 + (q4 & 1) * 8);
                unsigned b0, b1;
                ldsm_x2(b0, b1, baddr);
                mma16816(d[0][nt], a[0], b0, b1);
                mma16816(d[1][nt], a[1], b0, b1);
            }
        }
        #pragma unroll
        for (int mt = 0; mt < 2; ++mt) {
            int e = w * 32 + mt * 16 + gid;
            #pragma unroll
            for (int nt = 0; nt < 8; ++nt) {
                int i = nt * 8 + 2 * tg;
                ysT[ i      * LDY + e    ] = __float2half(d[mt][nt][0]);
                ysT[(i + 1) * LDY + e    ] = __float2half(d[mt][nt][1]);
                ysT[ i      * LDY + e + 8] = __float2half(d[mt][nt][2]);
                ysT[(i + 1) * LDY + e + 8] = __float2half(d[mt][nt][3]);
            }
        }
    }
    __syncthreads();

    // ---------------- Phase 4: out = Wv @ y via MMA + epilogue -------------
    // warp w: c-strip [32w, 32w+32), all 64 i, K=256. A from packed global Wv.
    {
        float d[2][8][4];
        #pragma unroll
        for (int mt = 0; mt < 2; ++mt)
            #pragma unroll
            for (int nt = 0; nt < 8; ++nt)
                #pragma unroll
                for (int r = 0; r < 4; ++r) d[mt][nt][r] = 0.f;

        const int q4   = lane >> 3;
        const int row8 = lane & 7;

        #pragma unroll
        for (int ks = 0; ks < 16; ++ks) {
            uint4 av0 = Wv_pk4[((w * 2 + 0) * 16 + ks) * 32 + lane];
            uint4 av1 = Wv_pk4[((w * 2 + 1) * 16 + ks) * 32 + lane];
            const int e0 = ks * 16;
            #pragma unroll
            for (int nt = 0; nt < 8; ++nt) {
                unsigned baddr = cvsm(ysT + (nt * 8 + row8) * LDY + e0 + (q4 & 1) * 8);
                unsigned b0, b1;
                ldsm_x2(b0, b1, baddr);
                mma16816(d[0][nt], (const unsigned*)&av0, b0, b1);
                mma16816(d[1][nt], (const unsigned*)&av1, b0, b1);
            }
        }

        const float g = gamma[0];
        float* ob = out + (size_t)bi * Cc * Hh * Ww;
        #pragma unroll
        for (int mt = 0; mt < 2; ++mt) {
            int cA = w * 32 + mt * 16 + gid;
            int cB = cA + 8;
            float bvA = bv[cA], bvB = bv[cB];
            #pragma unroll
            for (int nt = 0; nt < 8; ++nt) {
                int gy = hi * Aa + nt;           // i = nt*8 + 2tg -> iy = nt
                int gx = wi * Aa + 2 * tg;
                if (gy < Hh && gx + 1 < Ww) {
                    size_t oA = ((size_t)cA * Hh + gy) * Ww + gx;
                    size_t oB = ((size_t)cB * Hh + gy) * Ww + gx;
                    float2 rA = *(const float2*)(xb + oA);   // residual (L2-hit re-read)
                    float2 rB = *(const float2*)(xb + oB);
                    float2 sA, sB;
                    sA.x = g * (d[mt][nt][0] + bvA) + rA.x;
                    sA.y = g * (d[mt][nt][1] + bvA) + rA.y;
                    sB.x = g * (d[mt][nt][2] + bvB) + rB.x;
                    sB.y = g * (d[mt][nt][3] + bvB) + rB.y;
                    *(float2*)(ob + oA) = sA;
                    *(float2*)(ob + oB) = sB;
                }
            }
        }
    }
}

extern "C" void kernel_launch(void* const* d_in, const int* in_sizes, int n_in,
                              void* d_out, int out_size) {
    (void)in_sizes; (void)n_in; (void)out_size;
    const float* x     = (const float*)d_in[0];
    const float* Wq    = (const float*)d_in[1];
    const float* bq    = (const float*)d_in[2];
    const float* Wk    = (const float*)d_in[3];
    const float* bk    = (const float*)d_in[4];
    const float* Wv    = (const float*)d_in[5];
    const float* bv    = (const float*)d_in[6];
    const float* gamma = (const float*)d_in[7];
    float* out = (float*)d_out;

    cudaFuncSetAttribute(area_attn_kernel,
                         cudaFuncAttributeMaxDynamicSharedMemorySize, SMEM_BYTES);

    prep_pack<<<160, 256>>>(Wq, Wk, Wv);
    area_attn_kernel<<<4096, 256, SMEM_BYTES>>>(x, bq, bk, bv, gamma, out);
}

// round 10
// speedup vs baseline: 6.7580x; 1.3904x over previous
#include <cuda_runtime.h>
#include <cuda_fp16.h>

// AreaSelfAttention fused kernel, round 9:
//   ALL GEMMs (q/k conv, logits, y, Wv) on tensor cores; softmax on fragments
//   (fp32 exp, cross-half combine via tiny smem scratch).
// out = gamma * (Wv @ (Xw @ attn^T) + bv) + x

#define Cc   256
#define Hh   252
#define Ww   252
#define Aa   8
#define LDH  72     // row stride (halves) for all fp16 arrays -> 144B rows, ldmatrix conflict-free

// smem byte offsets (total 93184 B -> 2 CTAs/SM)
#define OFF_QKH  0                              // qkh[64][LDH]h : q rows 0..31, k rows 32..63
#define OFF_ATH  (OFF_QKH + 64 * LDH * 2)       //  9216: ath[64][LDH]h attn[i][j]
#define OFF_RED  (OFF_ATH + 64 * LDH * 2)       // 18432: redmax[2][64]f + redsum[2][64]f
#define OFF_XH   (OFF_RED + 1024)               // 19456: Xh[256][LDH]h window
#define OFF_Y    (OFF_XH + Cc * LDH * 2)        // 56320: y[256][LDH]h  y[e][i]
#define SMEM_BYTES (OFF_Y + Cc * LDH * 2)       // 93184

// Fragment-packed fp16 weights (prep kernel fills once per launch).
// reg r of lane = A[mt*16 + gid + 8*(r&1)][ks*16 + 2*tg + 8*(r>>1)]
__device__ uint4 Wqk_pk4[4 * 16 * 32];     // [Wq;Wk] 64x256
__device__ uint4 Wv_pk4[16 * 16 * 32];     // Wv 256x256

__global__ void prep_pack(const float* __restrict__ Wq,
                          const float* __restrict__ Wk,
                          const float* __restrict__ Wv) {
    int u = blockIdx.x * 256 + threadIdx.x;      // grid 160 -> 40960 b32 outputs
    if (u < 8192) {
        int r = u & 3, lane = (u >> 2) & 31, ks = (u >> 7) & 15, mt = u >> 11;
        int gid = lane >> 2, tg = lane & 3;
        int row = mt * 16 + gid + 8 * (r & 1);
        int col = ks * 16 + 2 * tg + 8 * (r >> 1);
        const float* src = (row < 32) ? (Wq + row * Cc) : (Wk + (row - 32) * Cc);
        __half2 h = __floats2half2_rn(src[col], src[col + 1]);
        ((unsigned*)Wqk_pk4)[u] = *(unsigned*)&h;
    } else {
        int v = u - 8192;
        int r = v & 3, lane = (v >> 2) & 31, ks = (v >> 7) & 15, mt = v >> 11;
        int gid = lane >> 2, tg = lane & 3;
        int row = mt * 16 + gid + 8 * (r & 1);
        int col = ks * 16 + 2 * tg + 8 * (r >> 1);
        const float* src = Wv + (size_t)row * Cc;
        __half2 h = __floats2half2_rn(src[col], src[col + 1]);
        ((unsigned*)Wv_pk4)[v] = *(unsigned*)&h;
    }
}

static __device__ __forceinline__ void mma16816(float* d, const unsigned* a,
                                                unsigned b0, unsigned b1) {
    asm volatile(
        "mma.sync.aligned.m16n8k16.row.col.f32.f16.f16.f32 "
        "{%0,%1,%2,%3}, {%4,%5,%6,%7}, {%8,%9}, {%0,%1,%2,%3};"
        : "+f"(d[0]), "+f"(d[1]), "+f"(d[2]), "+f"(d[3])
        : "r"(a[0]), "r"(a[1]), "r"(a[2]), "r"(a[3]), "r"(b0), "r"(b1));
}
static __device__ __forceinline__ unsigned cvsm(const void* p) {
    return (unsigned)__cvta_generic_to_shared(p);
}
static __device__ __forceinline__ void ldsm_x2(unsigned& r0, unsigned& r1, unsigned a) {
    asm volatile("ldmatrix.sync.aligned.m8n8.x2.shared.b16 {%0,%1}, [%2];"
                 : "=r"(r0), "=r"(r1) : "r"(a));
}
static __device__ __forceinline__ void ldsm_x2t(unsigned& r0, unsigned& r1, unsigned a) {
    asm volatile("ldmatrix.sync.aligned.m8n8.x2.trans.shared.b16 {%0,%1}, [%2];"
                 : "=r"(r0), "=r"(r1) : "r"(a));
}
static __device__ __forceinline__ void ldsm_x4(unsigned* r, unsigned a) {
    asm volatile("ldmatrix.sync.aligned.m8n8.x4.shared.b16 {%0,%1,%2,%3}, [%4];"
                 : "=r"(r[0]), "=r"(r[1]), "=r"(r[2]), "=r"(r[3]) : "r"(a));
}
static __device__ __forceinline__ void ldsm_x4t(unsigned* r, unsigned a) {
    asm volatile("ldmatrix.sync.aligned.m8n8.x4.trans.shared.b16 {%0,%1,%2,%3}, [%4];"
                 : "=r"(r[0]), "=r"(r[1]), "=r"(r[2]), "=r"(r[3]) : "r"(a));
}

__global__ __launch_bounds__(256, 2)
void area_attn_kernel(const float* __restrict__ x,
                      const float* __restrict__ bq, const float* __restrict__ bk,
                      const float* __restrict__ bv,
                      const float* __restrict__ gamma,
                      float* __restrict__ out)
{
    extern __shared__ char smraw[];
    __half* qkh    = (__half*)(smraw + OFF_QKH); // [64][LDH] q rows 0..31, k rows 32..63 (fp16)
    __half* ath    = (__half*)(smraw + OFF_ATH); // [64][LDH] attn fp16 (row i, col j)
    float*  redmax = (float*) (smraw + OFF_RED); // [2][64]
    float*  redsum = redmax + 128;               // [2][64]
    __half* Xh     = (__half*)(smraw + OFF_XH);  // [256][LDH] window fp16 (row c, col pos)
    __half* y      = (__half*)(smraw + OFF_Y);   // [256][LDH] y[e][i] fp16

    const int t   = threadIdx.x;
    const int blk = blockIdx.x;
    const int bi  = blk >> 10;                 // 4096 = 4 * 32 * 32
    const int hi  = (blk >> 5) & 31;
    const int wi  = blk & 31;

    const float* xb = x + (size_t)bi * Cc * Hh * Ww;

    // ---------------- Phase 0: load x window -> Xh (fp16, zero-padded) -----
    #pragma unroll
    for (int it = 0; it < 16; ++it) {
        int idx4 = t + (it << 8);
        int c    = idx4 >> 4;
        int rem  = idx4 & 15;
        int iy   = rem >> 1;
        int ix4  = (rem & 1) << 2;
        int gy   = hi * Aa + iy;
        int gx   = wi * Aa + ix4;
        float4 v = make_float4(0.f, 0.f, 0.f, 0.f);
        if (gy < Hh && gx + 3 < Ww)
            v = *(const float4*)(xb + ((size_t)c * Hh + gy) * Ww + gx);
        __half2 h0 = __floats2half2_rn(v.x, v.y);
        __half2 h1 = __floats2half2_rn(v.z, v.w);
        uint2 pk;
        pk.x = *(unsigned*)&h0; pk.y = *(unsigned*)&h1;
        *(uint2*)(Xh + c * LDH + (rem << 2)) = pk;
    }
    __syncthreads();

    const int w    = t >> 5;
    const int lane = t & 31;
    const int gid  = lane >> 2;
    const int tg   = lane & 3;
    const int q4   = lane >> 3;
    const int row8 = lane & 7;

    // ---------------- Phase 1: qkh = fp16([Wq;Wk] @ Xw + bias) via MMA -----
    // warp w: m-tile (w&3), n-half (w>>2)*32 positions, K=256.
    {
        const int mt1   = w & 3;
        const int nbase = (w >> 2) * 32;
        float d[4][4];
        #pragma unroll
        for (int nt = 0; nt < 4; ++nt)
            #pragma unroll
            for (int r = 0; r < 4; ++r) d[nt][r] = 0.f;

        #pragma unroll
        for (int ks = 0; ks < 16; ++ks) {
            uint4 av = Wqk_pk4[(mt1 * 16 + ks) * 32 + lane];
            unsigned baddr = cvsm(Xh + (ks * 16 + (lane & 15)) * LDH + nbase);
            #pragma unroll
            for (int nt = 0; nt < 4; ++nt) {
                unsigned b0, b1;
                ldsm_x2t(b0, b1, baddr + nt * 16);
                mma16816(d[nt], (const unsigned*)&av, b0, b1);
            }
        }
        const int oc0 = mt1 * 16 + gid;
        const int oc1 = oc0 + 8;
        float bb0 = (mt1 < 2) ? bq[oc0] : bk[oc0 - 32];
        float bb1 = (mt1 < 2) ? bq[oc1] : bk[oc1 - 32];
        #pragma unroll
        for (int nt = 0; nt < 4; ++nt) {
            int pos = nbase + nt * 8 + 2 * tg;
            __half2 hA = __floats2half2_rn(d[nt][0] + bb0, d[nt][1] + bb0);
            __half2 hB = __floats2half2_rn(d[nt][2] + bb1, d[nt][3] + bb1);
            *(__half2*)(qkh + oc0 * LDH + pos) = hA;
            *(__half2*)(qkh + oc1 * LDH + pos) = hB;
        }
    }
    __syncthreads();

    // ---------------- Phase 2: logits via MMA + fragment softmax -----------
    // warp w: i-tile mt2 = w&3 (16 rows), j-half h2 = w>>2 (32 cols), K=32.
    {
        const int mt2   = w & 3;
        const int h2    = w >> 2;
        const int jbase = h2 * 32;
        float d[4][4];
        #pragma unroll
        for (int nt = 0; nt < 4; ++nt)
            #pragma unroll
            for (int r = 0; r < 4; ++r) d[nt][r] = 0.f;

        #pragma unroll
        for (int ks = 0; ks < 2; ++ks) {
            // A = q^T : trans-load from qkh rows c (0..31), cols i
            unsigned a[4];
            unsigned aaddr = cvsm(qkh + (ks * 16 + (q4 >> 1) * 8 + row8) * LDH
                                      + mt2 * 16 + (q4 & 1) * 8);
            ldsm_x4t(a, aaddr);
            // B = k (rows c = k-dim), cols j
            unsigned baddr = cvsm(qkh + (32 + ks * 16 + (lane & 15)) * LDH + jbase);
            #pragma unroll
            for (int nt = 0; nt < 4; ++nt) {
                unsigned b0, b1;
                ldsm_x2t(b0, b1, baddr + nt * 16);
                mma16816(d[nt], a, b0, b1);
            }
        }

        const int iA = mt2 * 16 + gid;
        const int iB = iA + 8;
        // warp-partial row max (over this warp's 32 cols)
        float mA = d[0][0], mB = d[0][2];
        #pragma unroll
        for (int nt = 0; nt < 4; ++nt) {
            mA = fmaxf(mA, fmaxf(d[nt][0], d[nt][1]));
            mB = fmaxf(mB, fmaxf(d[nt][2], d[nt][3]));
        }
        mA = fmaxf(mA, __shfl_xor_sync(0xffffffffu, mA, 1));
        mA = fmaxf(mA, __shfl_xor_sync(0xffffffffu, mA, 2));
        mB = fmaxf(mB, __shfl_xor_sync(0xffffffffu, mB, 1));
        mB = fmaxf(mB, __shfl_xor_sync(0xffffffffu, mB, 2));
        if (tg == 0) { redmax[h2 * 64 + iA] = mA; redmax[h2 * 64 + iB] = mB; }
        __syncthreads();
        float gA = fmaxf(redmax[iA], redmax[64 + iA]);
        float gB = fmaxf(redmax[iB], redmax[64 + iB]);
        float sA = 0.f, sB = 0.f;
        #pragma unroll
        for (int nt = 0; nt < 4; ++nt) {
            d[nt][0] = __expf(d[nt][0] - gA); sA += d[nt][0];
            d[nt][1] = __expf(d[nt][1] - gA); sA += d[nt][1];
            d[nt][2] = __expf(d[nt][2] - gB); sB += d[nt][2];
            d[nt][3] = __expf(d[nt][3] - gB); sB += d[nt][3];
        }
        sA += __shfl_xor_sync(0xffffffffu, sA, 1);
        sA += __shfl_xor_sync(0xffffffffu, sA, 2);
        sB += __shfl_xor_sync(0xffffffffu, sB, 1);
        sB += __shfl_xor_sync(0xffffffffu, sB, 2);
        if (tg == 0) { redsum[h2 * 64 + iA] = sA; redsum[h2 * 64 + iB] = sB; }
        __syncthreads();
        float invA = 1.0f / (redsum[iA] + redsum[64 + iA]);
        float invB = 1.0f / (redsum[iB] + redsum[64 + iB]);
        #pragma unroll
        for (int nt = 0; nt < 4; ++nt) {
            int j = jbase + nt * 8 + 2 * tg;
            *(__half2*)(ath + iA * LDH + j) =
                __floats2half2_rn(d[nt][0] * invA, d[nt][1] * invA);
            *(__half2*)(ath + iB * LDH + j) =
                __floats2half2_rn(d[nt][2] * invB, d[nt][3] * invB);
        }
    }
    __syncthreads();

    // ---------------- Phase 3: y = Xw @ attn^T via MMA; store y[e][i] ------
    // warp w: e-strip [32w, 32w+32), all 64 i, K=64.
    {
        float d[2][8][4];
        #pragma unroll
        for (int mt = 0; mt < 2; ++mt)
            #pragma unroll
            for (int nt = 0; nt < 8; ++nt)
                #pragma unroll
                for (int r = 0; r < 4; ++r) d[mt][nt][r] = 0.f;

        #pragma unroll
        for (int ks = 0; ks < 4; ++ks) {
            const int j0 = ks * 16;
            unsigned a[2][4];
            #pragma unroll
            for (int mt = 0; mt < 2; ++mt) {
                unsigned addr = cvsm(Xh + (w * 32 + mt * 16 + (q4 & 1) * 8 + row8) * LDH
                                        + j0 + (q4 >> 1) * 8);
                ldsm_x4(a[mt], addr);
            }
            #pragma unroll
            for (int nt = 0; nt < 8; ++nt) {
                unsigned baddr = cvsm(ath + (nt * 8 + row8) * LDH + j0 + (q4 & 1) * 8);
                unsigned b0, b1;
                ldsm_x2(b0, b1, baddr);
                mma16816(d[0][nt], a[0], b0, b1);
                mma16816(d[1][nt], a[1], b0, b1);
            }
        }
        #pragma unroll
        for (int mt = 0; mt < 2; ++mt) {
            int e = w * 32 + mt * 16 + gid;
            #pragma unroll
            for (int nt = 0; nt < 8; ++nt) {
                int i = nt * 8 + 2 * tg;
                *(__half2*)(y +  e      * LDH + i) = __floats2half2_rn(d[mt][nt][0], d[mt][nt][1]);
                *(__half2*)(y + (e + 8) * LDH + i) = __floats2half2_rn(d[mt][nt][2], d[mt][nt][3]);
            }
        }
    }
    __syncthreads();

    // ---------------- Phase 4: out = Wv @ y via MMA + epilogue -------------
    // warp w: c-strip [32w, 32w+32), all 64 i, K=256. A from packed global Wv.
    // B = y^T fragments via trans-ldmatrix of y[e][i].
    {
        float d[2][8][4];
        #pragma unroll
        for (int mt = 0; mt < 2; ++mt)
            #pragma unroll
            for (int nt = 0; nt < 8; ++nt)
                #pragma unroll
                for (int r = 0; r < 4; ++r) d[mt][nt][r] = 0.f;

        #pragma unroll
        for (int ks = 0; ks < 16; ++ks) {
            uint4 av0 = Wv_pk4[((w * 2 + 0) * 16 + ks) * 32 + lane];
            uint4 av1 = Wv_pk4[((w * 2 + 1) * 16 + ks) * 32 + lane];
            const int e0 = ks * 16;
            unsigned baddr = cvsm(y + (e0 + (lane & 15)) * LDH);
            #pragma unroll
            for (int nt = 0; nt < 8; ++nt) {
                unsigned b0, b1;
                ldsm_x2t(b0, b1, baddr + nt * 16);
                mma16816(d[0][nt], (const unsigned*)&av0, b0, b1);
                mma16816(d[1][nt], (const unsigned*)&av1, b0, b1);
            }
        }

        const float g = gamma[0];
        float* ob = out + (size_t)bi * Cc * Hh * Ww;
        #pragma unroll
        for (int mt = 0; mt < 2; ++mt) {
            int cA = w * 32 + mt * 16 + gid;
            int cB = cA + 8;
            float bvA = bv[cA], bvB = bv[cB];
            #pragma unroll
            for (int nt = 0; nt < 8; ++nt) {
                int gy = hi * Aa + nt;           // i = nt*8 + 2tg -> iy = nt
                int gx = wi * Aa + 2 * tg;
                if (gy < Hh && gx + 1 < Ww) {
                    size_t oA = ((size_t)cA * Hh + gy) * Ww + gx;
                    size_t oB = ((size_t)cB * Hh + gy) * Ww + gx;
                    float2 rA = *(const float2*)(xb + oA);   // residual (L2-hit re-read)
                    float2 rB = *(const float2*)(xb + oB);
                    float2 sA, sB;
                    sA.x = g * (d[mt][nt][0] + bvA) + rA.x;
                    sA.y = g * (d[mt][nt][1] + bvA) + rA.y;
                    sB.x = g * (d[mt][nt][2] + bvB) + rB.x;
                    sB.y = g * (d[mt][nt][3] + bvB) + rB.y;
                    *(float2*)(ob + oA) = sA;
                    *(float2*)(ob + oB) = sB;
                }
            }
        }
    }
}

extern "C" void kernel_launch(void* const* d_in, const int* in_sizes, int n_in,
                              void* d_out, int out_size) {
    (void)in_sizes; (void)n_in; (void)out_size;
    const float* x     = (const float*)d_in[0];
    const float* Wq    = (const float*)d_in[1];
    const float* bq    = (const float*)d_in[2];
    const float* Wk    = (const float*)d_in[3];
    const float* bk    = (const float*)d_in[4];
    const float* Wv    = (const float*)d_in[5];
    const float* bv    = (const float*)d_in[6];
    const float* gamma = (const float*)d_in[7];
    float* out = (float*)d_out;

    cudaFuncSetAttribute(area_attn_kernel,
                         cudaFuncAttributeMaxDynamicSharedMemorySize, SMEM_BYTES);

    prep_pack<<<160, 256>>>(Wq, Wk, Wv);
    area_attn_kernel<<<4096, 256, SMEM_BYTES>>>(x, bq, bk, bv, gamma, out);
}

// round 11
// speedup vs baseline: 6.8402x; 1.0122x over previous
#include <cuda_runtime.h>
#include <cuda_fp16.h>

// AreaSelfAttention fused kernel, round 11:
//   all GEMMs on tensor cores; x4 ldmatrix everywhere; prefetched weight LDGs;
//   single-sync fragment softmax (fp32 exp).
// out = gamma * (Wv @ (Xw @ attn^T) + bv) + x

#define Cc   256
#define Hh   252
#define Ww   252
#define Aa   8
#define LDH  72     // row stride (halves) for all fp16 arrays -> 144B rows, ldmatrix conflict-free

// smem byte offsets (total 93184 B -> 2 CTAs/SM)
#define OFF_QKH  0                              // qkh[64][LDH]h : q rows 0..31, k rows 32..63
#define OFF_ATH  (OFF_QKH + 64 * LDH * 2)       //  9216: ath[64][LDH]h attn[i][j]
#define OFF_RED  (OFF_ATH + 64 * LDH * 2)       // 18432: red2[2][64] float2 (max, sum)
#define OFF_XH   (OFF_RED + 1024)               // 19456: Xh[256][LDH]h window
#define OFF_Y    (OFF_XH + Cc * LDH * 2)        // 56320: y[256][LDH]h  y[e][i]
#define SMEM_BYTES (OFF_Y + Cc * LDH * 2)       // 93184

// Fragment-packed fp16 weights (prep kernel fills once per launch).
// reg r of lane = A[mt*16 + gid + 8*(r&1)][ks*16 + 2*tg + 8*(r>>1)]
__device__ uint4 Wqk_pk4[4 * 16 * 32];     // [Wq;Wk] 64x256
__device__ uint4 Wv_pk4[16 * 16 * 32];     // Wv 256x256

__global__ void prep_pack(const float* __restrict__ Wq,
                          const float* __restrict__ Wk,
                          const float* __restrict__ Wv) {
    int u = blockIdx.x * 256 + threadIdx.x;      // grid 160 -> 40960 b32 outputs
    if (u < 8192) {
        int r = u & 3, lane = (u >> 2) & 31, ks = (u >> 7) & 15, mt = u >> 11;
        int gid = lane >> 2, tg = lane & 3;
        int row = mt * 16 + gid + 8 * (r & 1);
        int col = ks * 16 + 2 * tg + 8 * (r >> 1);
        const float* src = (row < 32) ? (Wq + row * Cc) : (Wk + (row - 32) * Cc);
        __half2 h = __floats2half2_rn(src[col], src[col + 1]);
        ((unsigned*)Wqk_pk4)[u] = *(unsigned*)&h;
    } else {
        int v = u - 8192;
        int r = v & 3, lane = (v >> 2) & 31, ks = (v >> 7) & 15, mt = v >> 11;
        int gid = lane >> 2, tg = lane & 3;
        int row = mt * 16 + gid + 8 * (r & 1);
        int col = ks * 16 + 2 * tg + 8 * (r >> 1);
        const float* src = Wv + (size_t)row * Cc;
        __half2 h = __floats2half2_rn(src[col], src[col + 1]);
        ((unsigned*)Wv_pk4)[v] = *(unsigned*)&h;
    }
}

static __device__ __forceinline__ void mma16816(float* d, const unsigned* a,
                                                unsigned b0, unsigned b1) {
    asm volatile(
        "mma.sync.aligned.m16n8k16.row.col.f32.f16.f16.f32 "
        "{%0,%1,%2,%3}, {%4,%5,%6,%7}, {%8,%9}, {%0,%1,%2,%3};"
        : "+f"(d[0]), "+f"(d[1]), "+f"(d[2]), "+f"(d[3])
        : "r"(a[0]), "r"(a[1]), "r"(a[2]), "r"(a[3]), "r"(b0), "r"(b1));
}
static __device__ __forceinline__ unsigned cvsm(const void* p) {
    return (unsigned)__cvta_generic_to_shared(p);
}
static __device__ __forceinline__ void ldsm_x4(unsigned* r, unsigned a) {
    asm volatile("ldmatrix.sync.aligned.m8n8.x4.shared.b16 {%0,%1,%2,%3}, [%4];"
                 : "=r"(r[0]), "=r"(r[1]), "=r"(r[2]), "=r"(r[3]) : "r"(a));
}
static __device__ __forceinline__ void ldsm_x4t(unsigned* r, unsigned a) {
    asm volatile("ldmatrix.sync.aligned.m8n8.x4.trans.shared.b16 {%0,%1,%2,%3}, [%4];"
                 : "=r"(r[0]), "=r"(r[1]), "=r"(r[2]), "=r"(r[3]) : "r"(a));
}

__global__ __launch_bounds__(256, 2)
void area_attn_kernel(const float* __restrict__ x,
                      const float* __restrict__ bq, const float* __restrict__ bk,
                      const float* __restrict__ bv,
                      const float* __restrict__ gamma,
                      float* __restrict__ out)
{
    extern __shared__ char smraw[];
    __half* qkh  = (__half*)(smraw + OFF_QKH); // [64][LDH] q rows 0..31, k rows 32..63 (fp16)
    __half* ath  = (__half*)(smraw + OFF_ATH); // [64][LDH] attn fp16 (row i, col j)
    float2* red2 = (float2*)(smraw + OFF_RED); // [2][64] (max, sum) per j-half per row
    __half* Xh   = (__half*)(smraw + OFF_XH);  // [256][LDH] window fp16 (row c, col pos)
    __half* y    = (__half*)(smraw + OFF_Y);   // [256][LDH] y[e][i] fp16

    const int t   = threadIdx.x;
    const int blk = blockIdx.x;
    const int bi  = blk >> 10;                 // 4096 = 4 * 32 * 32
    const int hi  = (blk >> 5) & 31;
    const int wi  = blk & 31;

    const float* xb = x + (size_t)bi * Cc * Hh * Ww;

    // ---------------- Phase 0: load x window -> Xh (fp16, zero-padded) -----
    #pragma unroll
    for (int it = 0; it < 16; ++it) {
        int idx4 = t + (it << 8);
        int c    = idx4 >> 4;
        int rem  = idx4 & 15;
        int iy   = rem >> 1;
        int ix4  = (rem & 1) << 2;
        int gy   = hi * Aa + iy;
        int gx   = wi * Aa + ix4;
        float4 v = make_float4(0.f, 0.f, 0.f, 0.f);
        if (gy < Hh && gx + 3 < Ww)
            v = *(const float4*)(xb + ((size_t)c * Hh + gy) * Ww + gx);
        __half2 h0 = __floats2half2_rn(v.x, v.y);
        __half2 h1 = __floats2half2_rn(v.z, v.w);
        uint2 pk;
        pk.x = *(unsigned*)&h0; pk.y = *(unsigned*)&h1;
        *(uint2*)(Xh + c * LDH + (rem << 2)) = pk;
    }
    __syncthreads();

    const int w    = t >> 5;
    const int lane = t & 31;
    const int gid  = lane >> 2;
    const int tg   = lane & 3;
    const int q4   = lane >> 3;
    const int row8 = lane & 7;
    const int l15  = lane & 15;
    const int lhi8 = (lane >> 4) << 3;     // 0 or 8

    // ---------------- Phase 1: qkh = fp16([Wq;Wk] @ Xw + bias) via MMA -----
    // warp w: m-tile (w&3), n-half (w>>2)*32 positions, K=256.
    {
        const int mt1   = w & 3;
        const int nbase = (w >> 2) * 32;
        float d[4][4];
        #pragma unroll
        for (int nt = 0; nt < 4; ++nt)
            #pragma unroll
            for (int r = 0; r < 4; ++r) d[nt][r] = 0.f;

        uint4 av = Wqk_pk4[(mt1 * 16) * 32 + lane];
        #pragma unroll
        for (int ks = 0; ks < 16; ++ks) {
            uint4 nx;
            if (ks < 15) nx = Wqk_pk4[(mt1 * 16 + ks + 1) * 32 + lane];
            unsigned baddr = cvsm(Xh + (ks * 16 + l15) * LDH + nbase + lhi8);
            #pragma unroll
            for (int ntp = 0; ntp < 2; ++ntp) {
                unsigned bb[4];
                ldsm_x4t(bb, baddr + ntp * 32);
                mma16816(d[2 * ntp],     (const unsigned*)&av, bb[0], bb[1]);
                mma16816(d[2 * ntp + 1], (const unsigned*)&av, bb[2], bb[3]);
            }
            if (ks < 15) av = nx;
        }
        const int oc0 = mt1 * 16 + gid;
        const int oc1 = oc0 + 8;
        float bb0 = (mt1 < 2) ? bq[oc0] : bk[oc0 - 32];
        float bb1 = (mt1 < 2) ? bq[oc1] : bk[oc1 - 32];
        #pragma unroll
        for (int nt = 0; nt < 4; ++nt) {
            int pos = nbase + nt * 8 + 2 * tg;
            __half2 hA = __floats2half2_rn(d[nt][0] + bb0, d[nt][1] + bb0);
            __half2 hB = __floats2half2_rn(d[nt][2] + bb1, d[nt][3] + bb1);
            *(__half2*)(qkh + oc0 * LDH + pos) = hA;
            *(__half2*)(qkh + oc1 * LDH + pos) = hB;
        }
    }
    __syncthreads();

    // ---------------- Phase 2: logits via MMA + single-sync softmax --------
    // warp w: i-tile mt2 = w&3 (16 rows), j-half h2 = w>>2 (32 cols), K=32.
    {
        const int mt2   = w & 3;
        const int h2    = w >> 2;
        const int jbase = h2 * 32;
        float d[4][4];
        #pragma unroll
        for (int nt = 0; nt < 4; ++nt)
            #pragma unroll
            for (int r = 0; r < 4; ++r) d[nt][r] = 0.f;

        #pragma unroll
        for (int ks = 0; ks < 2; ++ks) {
            // A = q^T : trans-load from qkh rows c (0..31), cols i
            unsigned a[4];
            unsigned aaddr = cvsm(qkh + (ks * 16 + (q4 >> 1) * 8 + row8) * LDH
                                      + mt2 * 16 + (q4 & 1) * 8);
            ldsm_x4t(a, aaddr);
            // B = k (rows c = k-dim), cols j: x4t covers two n-tiles
            unsigned baddr = cvsm(qkh + (32 + ks * 16 + l15) * LDH + jbase + lhi8);
            #pragma unroll
            for (int ntp = 0; ntp < 2; ++ntp) {
                unsigned bb[4];
                ldsm_x4t(bb, baddr + ntp * 32);
                mma16816(d[2 * ntp],     a, bb[0], bb[1]);
                mma16816(d[2 * ntp + 1], a, bb[2], bb[3]);
            }
        }

        const int iA = mt2 * 16 + gid;
        const int iB = iA + 8;
        // warp-local row max over this warp's 32 cols
        float mA = d[0][0], mB = d[0][2];
        #pragma unroll
        for (int nt = 0; nt < 4; ++nt) {
            mA = fmaxf(mA, fmaxf(d[nt][0], d[nt][1]));
            mB = fmaxf(mB, fmaxf(d[nt][2], d[nt][3]));
        }
        mA = fmaxf(mA, __shfl_xor_sync(0xffffffffu, mA, 1));
        mA = fmaxf(mA, __shfl_xor_sync(0xffffffffu, mA, 2));
        mB = fmaxf(mB, __shfl_xor_sync(0xffffffffu, mB, 1));
        mB = fmaxf(mB, __shfl_xor_sync(0xffffffffu, mB, 2));
        // exp against local max + local sum
        float sA = 0.f, sB = 0.f;
        #pragma unroll
        for (int nt = 0; nt < 4; ++nt) {
            d[nt][0] = __expf(d[nt][0] - mA); sA += d[nt][0];
            d[nt][1] = __expf(d[nt][1] - mA); sA += d[nt][1];
            d[nt][2] = __expf(d[nt][2] - mB); sB += d[nt][2];
            d[nt][3] = __expf(d[nt][3] - mB); sB += d[nt][3];
        }
        sA += __shfl_xor_sync(0xffffffffu, sA, 1);
        sA += __shfl_xor_sync(0xffffffffu, sA, 2);
        sB += __shfl_xor_sync(0xffffffffu, sB, 1);
        sB += __shfl_xor_sync(0xffffffffu, sB, 2);
        if (tg == 0) {
            red2[h2 * 64 + iA] = make_float2(mA, sA);
            red2[h2 * 64 + iB] = make_float2(mB, sB);
        }
        __syncthreads();
        // combine halves: global max + rescaled total, then own-half factor
        float2 c0A = red2[iA], c1A = red2[64 + iA];
        float2 c0B = red2[iB], c1B = red2[64 + iB];
        float gmA = fmaxf(c0A.x, c1A.x);
        float gmB = fmaxf(c0B.x, c1B.x);
        float totA = c0A.y * __expf(c0A.x - gmA) + c1A.y * __expf(c1A.x - gmA);
        float totB = c0B.y * __expf(c0B.x - gmB) + c1B.y * __expf(c1B.x - gmB);
        float facA = __expf(mA - gmA) / totA;
        float facB = __expf(mB - gmB) / totB;
        #pragma unroll
        for (int nt = 0; nt < 4; ++nt) {
            int j = jbase + nt * 8 + 2 * tg;
            *(__half2*)(ath + iA * LDH + j) =
                __floats2half2_rn(d[nt][0] * facA, d[nt][1] * facA);
            *(__half2*)(ath + iB * LDH + j) =
                __floats2half2_rn(d[nt][2] * facB, d[nt][3] * facB);
        }
    }
    __syncthreads();

    // ---------------- Phase 3: y = Xw @ attn^T via MMA; store y[e][i] ------
    // warp w: e-strip [32w, 32w+32), all 64 i, K=64.
    {
        float d[2][8][4];
        #pragma unroll
        for (int mt = 0; mt < 2; ++mt)
            #pragma unroll
            for (int nt = 0; nt < 8; ++nt)
                #pragma unroll
                for (int r = 0; r < 4; ++r) d[mt][nt][r] = 0.f;

        #pragma unroll
        for (int ks = 0; ks < 4; ++ks) {
            const int j0 = ks * 16;
            unsigned a[2][4];
            #pragma unroll
            for (int mt = 0; mt < 2; ++mt) {
                unsigned addr = cvsm(Xh + (w * 32 + mt * 16 + (q4 & 1) * 8 + row8) * LDH
                                        + j0 + (q4 >> 1) * 8);
                ldsm_x4(a[mt], addr);
            }
            #pragma unroll
            for (int ntp = 0; ntp < 4; ++ntp) {
                // x4 non-trans: m0,m1 = n-tile 2ntp (k lo/hi); m2,m3 = n-tile 2ntp+1
                unsigned baddr = cvsm(ath + (ntp * 16 + lhi8 + row8) * LDH
                                          + j0 + (q4 & 1) * 8);
                unsigned bb[4];
                ldsm_x4(bb, baddr);
                mma16816(d[0][2 * ntp],     a[0], bb[0], bb[1]);
                mma16816(d[0][2 * ntp + 1], a[0], bb[2], bb[3]);
                mma16816(d[1][2 * ntp],     a[1], bb[0], bb[1]);
                mma16816(d[1][2 * ntp + 1], a[1], bb[2], bb[3]);
            }
        }
        #pragma unroll
        for (int mt = 0; mt < 2; ++mt) {
            int e = w * 32 + mt * 16 + gid;
            #pragma unroll
            for (int nt = 0; nt < 8; ++nt) {
                int i = nt * 8 + 2 * tg;
                *(__half2*)(y +  e      * LDH + i) = __floats2half2_rn(d[mt][nt][0], d[mt][nt][1]);
                *(__half2*)(y + (e + 8) * LDH + i) = __floats2half2_rn(d[mt][nt][2], d[mt][nt][3]);
            }
        }
    }
    __syncthreads();

    // ---------------- Phase 4: out = Wv @ y via MMA + epilogue -------------
    // warp w: c-strip [32w, 32w+32), all 64 i, K=256. A prefetched from global.
    {
        float d[2][8][4];
        #pragma unroll
        for (int mt = 0; mt < 2; ++mt)
            #pragma unroll
            for (int nt = 0; nt < 8; ++nt)
                #pragma unroll
                for (int r = 0; r < 4; ++r) d[mt][nt][r] = 0.f;

        uint4 av0 = Wv_pk4[((w * 2 + 0) * 16) * 32 + lane];
        uint4 av1 = Wv_pk4[((w * 2 + 1) * 16) * 32 + lane];
        #pragma unroll
        for (int ks = 0; ks < 16; ++ks) {
            uint4 nx0, nx1;
            if (ks < 15) {
                nx0 = Wv_pk4[((w * 2 + 0) * 16 + ks + 1) * 32 + lane];
                nx1 = Wv_pk4[((w * 2 + 1) * 16 + ks + 1) * 32 + lane];
            }
            const int e0 = ks * 16;
            unsigned baddr = cvsm(y + (e0 + l15) * LDH + lhi8);
            #pragma unroll
            for (int ntp = 0; ntp < 4; ++ntp) {
                unsigned bb[4];
                ldsm_x4t(bb, baddr + ntp * 32);
                mma16816(d[0][2 * ntp],     (const unsigned*)&av0, bb[0], bb[1]);
                mma16816(d[0][2 * ntp + 1], (const unsigned*)&av0, bb[2], bb[3]);
                mma16816(d[1][2 * ntp],     (const unsigned*)&av1, bb[0], bb[1]);
                mma16816(d[1][2 * ntp + 1], (const unsigned*)&av1, bb[2], bb[3]);
            }
            if (ks < 15) { av0 = nx0; av1 = nx1; }
        }

        const float g = gamma[0];
        float* ob = out + (size_t)bi * Cc * Hh * Ww;
        #pragma unroll
        for (int mt = 0; mt < 2; ++mt) {
            int cA = w * 32 + mt * 16 + gid;
            int cB = cA + 8;
            float bvA = bv[cA], bvB = bv[cB];
            #pragma unroll
            for (int nt = 0; nt < 8; ++nt) {
                int gy = hi * Aa + nt;           // i = nt*8 + 2tg -> iy = nt
                int gx = wi * Aa + 2 * tg;
                if (gy < Hh && gx + 1 < Ww) {
                    size_t oA = ((size_t)cA * Hh + gy) * Ww + gx;
                    size_t oB = ((size_t)cB * Hh + gy) * Ww + gx;
                    float2 rA = *(const float2*)(xb + oA);   // residual (L2-hit re-read)
                    float2 rB = *(const float2*)(xb + oB);
                    float2 sA, sB;
                    sA.x = g * (d[mt][nt][0] + bvA) + rA.x;
                    sA.y = g * (d[mt][nt][1] + bvA) + rA.y;
                    sB.x = g * (d[mt][nt][2] + bvB) + rB.x;
                    sB.y = g * (d[mt][nt][3] + bvB) + rB.y;
                    *(float2*)(ob + oA) = sA;
                    *(float2*)(ob + oB) = sB;
                }
            }
        }
    }
}

extern "C" void kernel_launch(void* const* d_in, const int* in_sizes, int n_in,
                              void* d_out, int out_size) {
    (void)in_sizes; (void)n_in; (void)out_size;
    const float* x     = (const float*)d_in[0];
    const float* Wq    = (const float*)d_in[1];
    const float* bq    = (const float*)d_in[2];
    const float* Wk    = (const float*)d_in[3];
    const float* bk    = (const float*)d_in[4];
    const float* Wv    = (const float*)d_in[5];
    const float* bv    = (const float*)d_in[6];
    const float* gamma = (const float*)d_in[7];
    float* out = (float*)d_out;

    cudaFuncSetAttribute(area_attn_kernel,
                         cudaFuncAttributeMaxDynamicSharedMemorySize, SMEM_BYTES);

    prep_pack<<<160, 256>>>(Wq, Wk, Wv);
    area_attn_kernel<<<4096, 256, SMEM_BYTES>>>(x, bq, bk, bv, gamma, out);
}